// round 1
// baseline (speedup 1.0000x reference)
#include <cuda_runtime.h>
#include <stdint.h>

#define NB   16384
#define FDIM 2048
#define HID  256
#define NODES 9
#define NSD  2304   // 9*256

// ---------------- static scratch (allowed: __device__ globals) ----------------
__device__ float g_ns0[NB * NSD];
__device__ float g_ns1[NB * NSD];
__device__ float g_agg[NB * NSD];
__device__ float g_wc[HID * 512];   // [256][512]: [:,0:256]=upd_w1, [:,256:512]=upd_w2@msg_w
__device__ float g_bc[HID];         // upd_b + upd_w2@msg_b

// ---------------- helpers ----------------
__device__ __forceinline__ float f2t(float x){
    uint32_t u; asm("cvt.rna.tf32.f32 %0, %1;" : "=r"(u) : "f"(x));
    return __uint_as_float(u);
}
__device__ __forceinline__ float4 f2t4(float4 v){
    v.x=f2t(v.x); v.y=f2t(v.y); v.z=f2t(v.z); v.w=f2t(v.w); return v;
}
__device__ __forceinline__ void mma8(float c[4], const uint32_t a[4], uint32_t b0, uint32_t b1){
    asm volatile(
        "mma.sync.aligned.m16n8k8.row.col.f32.tf32.tf32.f32 "
        "{%0,%1,%2,%3},{%4,%5,%6,%7},{%8,%9},{%0,%1,%2,%3};\n"
        : "+f"(c[0]),"+f"(c[1]),"+f"(c[2]),"+f"(c[3])
        : "r"(a[0]),"r"(a[1]),"r"(a[2]),"r"(a[3]),"r"(b0),"r"(b1));
}
__device__ __forceinline__ float4 f4add(float4 a, float4 b){
    a.x+=b.x; a.y+=b.y; a.z+=b.z; a.w+=b.w; return a;
}
__device__ __forceinline__ float4 f4sub(float4 a, float4 b){
    a.x-=b.x; a.y-=b.y; a.z-=b.z; a.w-=b.w; return a;
}
__device__ __forceinline__ float4 f4scale(float4 a, float s){
    a.x*=s; a.y*=s; a.z*=s; a.w*=s; return a;
}

// ---------------- weight folding: Wc = [upd_w1 | upd_w2@msg_w], bc = upd_b + upd_w2@msg_b ----------------
__global__ void prep_k(const float* __restrict__ msgw, const float* __restrict__ msgb,
                       const float* __restrict__ updw, const float* __restrict__ updb){
    int o = blockIdx.x, t = threadIdx.x;
    __shared__ float u2[HID];
    u2[t] = updw[o*512 + 256 + t];
    __syncthreads();
    g_wc[o*512 + t] = updw[o*512 + t];
    float s = 0.f;
    #pragma unroll 8
    for (int j = 0; j < HID; j++) s += u2[j] * msgw[j*HID + t];
    g_wc[o*512 + 256 + t] = s;
    if (t == 0){
        float sb = 0.f;
        for (int j = 0; j < HID; j++) sb += u2[j] * msgb[j];
        g_bc[o] = updb[o] + sb;
    }
}

// ---------------- adjacency aggregation: agg[b,n,:] = sum_j A[n,j] ns[b,j,:] ----------------
// A (row-normalized): row0 = all/9; row1 = (v0+v1)/2; rows2..6 = (v0+vi+v7+v8)/4; rows7,8 = (sum - v1)/8
__global__ void __launch_bounds__(256) agg_k(int sel){
    const float* __restrict__ src = sel ? g_ns1 : g_ns0;
    int idx = blockIdx.x*256 + threadIdx.x;           // over NB*64
    int b = idx >> 6, h4 = (idx & 63) << 2;
    const float* base = src + b*NSD + h4;
    float4 v[9];
    #pragma unroll
    for (int j = 0; j < 9; j++) v[j] = *(const float4*)(base + j*HID);
    float4 sall = v[0];
    #pragma unroll
    for (int j = 1; j < 9; j++) sall = f4add(sall, v[j]);
    float* ob = g_agg + b*NSD + h4;
    *(float4*)(ob + 0*HID) = f4scale(sall, 1.f/9.f);
    *(float4*)(ob + 1*HID) = f4scale(f4add(v[0], v[1]), 0.5f);
    float4 b06 = f4add(v[0], f4add(v[7], v[8]));
    #pragma unroll
    for (int i = 2; i <= 6; i++)
        *(float4*)(ob + i*HID) = f4scale(f4add(b06, v[i]), 0.25f);
    float4 r78 = f4scale(f4sub(sall, v[1]), 0.125f);
    *(float4*)(ob + 7*HID) = r78;
    *(float4*)(ob + 8*HID) = r78;
}

// ---------------- tf32 GEMM: MODE 0 = init (conc @ f2n_w.T + biases), MODE 1 = step ----------------
// CTA tile 128x128x32, 8 warps (2x4), warp tile 64x32, m16n8k8 tf32 fragments.
// Single smem buffer + register-staged global prefetch (rounding to tf32 at STS).
template<int MODE>
__global__ void __launch_bounds__(256) gemm_k(
    const float* __restrict__ Ag, const float* __restrict__ Bg,
    const float* __restrict__ bias, const float* __restrict__ logits,
    const float* __restrict__ encw, const float* __restrict__ encb,
    int sel)
{
    constexpr int KB = (MODE==0) ? FDIM : 512;
    constexpr int NT = KB / 32;

    __shared__ float As[128*36];
    __shared__ float Bs[128*36];

    const float* Asrc; const float* Asrc2 = nullptr; const float* Bsrc; float* Cdst;
    if constexpr (MODE==0){ Asrc = Ag; Bsrc = Bg; Cdst = g_ns0; }
    else { Asrc = sel ? g_ns1 : g_ns0; Asrc2 = g_agg; Bsrc = g_wc; Cdst = sel ? g_ns0 : g_ns1; }

    const int tid = threadIdx.x;
    const int ldr = tid >> 3, ldc = (tid & 7) * 4;
    const int row0 = blockIdx.y * 128, col0 = blockIdx.x * 128;

    int abase[4], bbase[4];
    #pragma unroll
    for (int i = 0; i < 4; i++){
        int r = row0 + ldr + 32*i;
        if constexpr (MODE==0) abase[i] = r*FDIM + ldc;
        else                   abase[i] = (r/9)*NSD + (r%9)*HID + ldc;
        int nr = col0 + ldr + 32*i;
        bbase[i] = nr*KB + ldc;
    }

    float acc[4][4][4];
    #pragma unroll
    for (int i0=0;i0<4;i0++)
        #pragma unroll
        for (int i1=0;i1<4;i1++)
            #pragma unroll
            for (int i2=0;i2<4;i2++) acc[i0][i1][i2] = 0.f;

    const int wid = tid >> 5, lane = tid & 31, g = lane >> 2, tg = lane & 3;
    const int mb = (wid & 1) * 64, nb = (wid >> 1) * 32;

    float4 ra[4], rb[4];
    #pragma unroll
    for (int i = 0; i < 4; i++){
        ra[i] = *(const float4*)(Asrc + abase[i]);
        rb[i] = *(const float4*)(Bsrc + bbase[i]);
    }
    #pragma unroll
    for (int i = 0; i < 4; i++){
        *(float4*)&As[(ldr+32*i)*36 + ldc] = f2t4(ra[i]);
        *(float4*)&Bs[(ldr+32*i)*36 + ldc] = f2t4(rb[i]);
    }
    __syncthreads();

    for (int kt = 0; kt < NT; kt++){
        if (kt + 1 < NT){
            const int kn = kt + 1;
            #pragma unroll
            for (int i = 0; i < 4; i++){
                if constexpr (MODE==0){
                    ra[i] = *(const float4*)(Asrc + abase[i] + kn*32);
                } else {
                    const float* s = (kn < 8) ? Asrc : Asrc2;
                    ra[i] = *(const float4*)(s + abase[i] + (kn & 7)*32);
                }
                rb[i] = *(const float4*)(Bsrc + bbase[i] + kn*32);
            }
        }
        #pragma unroll
        for (int ks = 0; ks < 4; ks++){
            const int k0 = ks * 8;
            uint32_t a[4][4]; uint32_t bf[4][2];
            #pragma unroll
            for (int fm = 0; fm < 4; fm++){
                int m0 = (mb + fm*16 + g)*36 + k0 + tg;
                a[fm][0] = __float_as_uint(As[m0]);
                a[fm][1] = __float_as_uint(As[m0 + 8*36]);
                a[fm][2] = __float_as_uint(As[m0 + 4]);
                a[fm][3] = __float_as_uint(As[m0 + 8*36 + 4]);
            }
            #pragma unroll
            for (int fn = 0; fn < 4; fn++){
                int n0 = (nb + fn*8 + g)*36 + k0 + tg;
                bf[fn][0] = __float_as_uint(Bs[n0]);
                bf[fn][1] = __float_as_uint(Bs[n0 + 4]);
            }
            #pragma unroll
            for (int fm = 0; fm < 4; fm++)
                #pragma unroll
                for (int fn = 0; fn < 4; fn++)
                    mma8(acc[fm][fn], a[fm], bf[fn][0], bf[fn][1]);
        }
        __syncthreads();
        if (kt + 1 < NT){
            #pragma unroll
            for (int i = 0; i < 4; i++){
                *(float4*)&As[(ldr+32*i)*36 + ldc] = f2t4(ra[i]);
                *(float4*)&Bs[(ldr+32*i)*36 + ldc] = f2t4(rb[i]);
            }
            __syncthreads();
        }
    }

    // epilogue
    #pragma unroll
    for (int fm = 0; fm < 4; fm++){
        const int gm = row0 + mb + fm*16 + g;
        int cb0, cb1;
        if constexpr (MODE==0){ cb0 = gm*NSD; cb1 = (gm+8)*NSD; }
        else {
            const int g2 = gm + 8;
            cb0 = (gm/9)*NSD + (gm%9)*HID;
            cb1 = (g2/9)*NSD + (g2%9)*HID;
        }
        #pragma unroll
        for (int fn = 0; fn < 4; fn++){
            const int gn = col0 + nb + fn*8 + 2*tg;
            float2 v0, v1;
            if constexpr (MODE==0){
                const int node = gn >> 8, h = gn & 255;
                const float lg0 = logits[gm*9 + node], lg1 = logits[(gm+8)*9 + node];
                const float a0 = bias[gn]   + encb[h];
                const float a1 = bias[gn+1] + encb[h+1];
                const float e0 = encw[h], e1 = encw[h+1];
                v0.x = acc[fm][fn][0] + a0 + lg0*e0;
                v0.y = acc[fm][fn][1] + a1 + lg0*e1;
                v1.x = acc[fm][fn][2] + a0 + lg1*e0;
                v1.y = acc[fm][fn][3] + a1 + lg1*e1;
            } else {
                const float b0 = g_bc[gn], b1 = g_bc[gn+1];
                v0.x = tanhf(acc[fm][fn][0] + b0);
                v0.y = tanhf(acc[fm][fn][1] + b1);
                v1.x = tanhf(acc[fm][fn][2] + b0);
                v1.y = tanhf(acc[fm][fn][3] + b1);
            }
            *(float2*)&Cdst[cb0 + gn] = v0;
            *(float2*)&Cdst[cb1 + gn] = v1;
        }
    }
}

// ---------------- output heads: nodes 7 (chronic) and 8 (acute+chronic) ----------------
__global__ void __launch_bounds__(256) out_k(const float* __restrict__ outw,
                                             const float* __restrict__ outb,
                                             float* __restrict__ out){
    int wid = threadIdx.x >> 5, lane = threadIdx.x & 31;
    int b = blockIdx.x * 8 + wid;
    const float* r7 = g_ns0 + b*NSD + 7*HID;
    float s7 = 0.f, s8 = 0.f;
    #pragma unroll
    for (int i = lane; i < HID; i += 32){
        float w = outw[i];
        s7 += r7[i] * w;
        s8 += r7[i + HID] * w;
    }
    #pragma unroll
    for (int o = 16; o > 0; o >>= 1){
        s7 += __shfl_xor_sync(0xffffffffu, s7, o);
        s8 += __shfl_xor_sync(0xffffffffu, s8, o);
    }
    if (lane == 0){
        out[b]      = s7 + outb[0];
        out[NB + b] = s8 + outb[0];
    }
}

// ---------------- launch ----------------
extern "C" void kernel_launch(void* const* d_in, const int* in_sizes, int n_in,
                              void* d_out, int out_size){
    const float* conc   = (const float*)d_in[0];
    const float* logits = (const float*)d_in[1];
    const float* encw   = (const float*)d_in[2];
    const float* encb   = (const float*)d_in[3];
    const float* f2nw   = (const float*)d_in[4];
    const float* f2nb   = (const float*)d_in[5];
    const float* msgw   = (const float*)d_in[6];
    const float* msgb   = (const float*)d_in[7];
    const float* updw   = (const float*)d_in[8];
    const float* updb   = (const float*)d_in[9];
    const float* outw   = (const float*)d_in[10];
    const float* outb   = (const float*)d_in[11];
    float* out = (float*)d_out;

    prep_k<<<256, 256>>>(msgw, msgb, updw, updb);

    // init: node_states = conc@f2n_w.T + f2n_b + logits*enc_w + enc_b  -> g_ns0
    gemm_k<0><<<dim3(NSD/128, NB/128), 256>>>(conc, f2nw, f2nb, logits, encw, encb, 0);

    // 4 message-passing steps (ping-pong ns0/ns1), folded single-GEMM form
    for (int s = 0; s < 4; s++){
        agg_k<<<(NB*64)/256, 256>>>(s & 1);
        gemm_k<1><<<dim3(2, (NB*NODES)/128), 256>>>(nullptr, nullptr, nullptr,
                                                    nullptr, nullptr, nullptr, s & 1);
    }

    out_k<<<NB/8, 256>>>(outw, outb, out);
}